// round 9
// baseline (speedup 1.0000x reference)
#include <cuda_runtime.h>
#include <cuda_fp16.h>
#include <stdint.h>

#define NB 32
#define NS 2048
#define NH 1024
#define MTOT (NB*NS)      // 65536 flattened (s,b) rows
#define NTILES 4          // NH / N_CTA
#define N_CTA 256
#define M_CTA 128
#define KCH 64            // k-chunk elems (128B rows in fp16)
#define NCHUNK (NH/KCH)   // 16
#define NSTAGE 3
#define NTHREADS 512

// smem: per stage A 16KB + B 32KB
#define SB_OFF 16384
#define STAGESZ 49152
#define SROW_OFF (NSTAGE*STAGESZ)
#define SMEM_TOTAL (NSTAGE*STAGESZ + 4096)

// persistent scratch
__device__ float g_hidc[NB*NH];
__device__ float g_part[NTILES*MTOT];
__device__ __align__(16) __half g_encF[MTOT*NH];   // 134 MB
__device__ __align__(16) __half g_w2F[NH*NH];      // 2 MB

// ---------------- helpers ----------------
__device__ __forceinline__ uint32_t smem_u32(const void* p){
    uint32_t a;
    asm("{ .reg .u64 t; cvta.to.shared.u64 t, %1; cvt.u32.u64 %0, t; }" : "=r"(a) : "l"(p));
    return a;
}
__device__ __forceinline__ void cp16(uint32_t dst, const void* src){
    asm volatile("cp.async.cg.shared.global [%0], [%1], 16;" :: "r"(dst), "l"(src));
}
__device__ __forceinline__ void cp_commit(){
    asm volatile("cp.async.commit_group;");
}
template<int N> __device__ __forceinline__ void cp_wait(){
    asm volatile("cp.async.wait_group %0;" :: "n"(N));
}
__device__ __forceinline__ void ldsm4(uint32_t r[4], uint32_t addr){
    asm volatile("ldmatrix.sync.aligned.m8n8.x4.shared.b16 {%0,%1,%2,%3}, [%4];\n"
        : "=r"(r[0]),"=r"(r[1]),"=r"(r[2]),"=r"(r[3]) : "r"(addr));
}
__device__ __forceinline__ void mma16816(float c[4], const uint32_t a[4], uint32_t b0, uint32_t b1){
    asm volatile("mma.sync.aligned.m16n8k16.row.col.f32.f16.f16.f32 "
        "{%0,%1,%2,%3}, {%4,%5,%6,%7}, {%8,%9}, {%0,%1,%2,%3};\n"
        : "+f"(c[0]),"+f"(c[1]),"+f"(c[2]),"+f"(c[3])
        : "r"(a[0]),"r"(a[1]),"r"(a[2]),"r"(a[3]),"r"(b0),"r"(b1));
}
__device__ __forceinline__ uint32_t h2u(__half2 v){ return *reinterpret_cast<uint32_t*>(&v); }

// ---------------------------------------------------------------------------
// K0a: enc fp32 -> fp16  (8 elems / thread)
// ---------------------------------------------------------------------------
__global__ void cvt_enc_kernel(const float* __restrict__ enc){
    size_t base = ((size_t)blockIdx.x * 256 + threadIdx.x) * 8;
    float4 v0 = *(const float4*)(enc + base);
    float4 v1 = *(const float4*)(enc + base + 4);
    __half2 h0 = __floats2half2_rn(v0.x, v0.y);
    __half2 h1 = __floats2half2_rn(v0.z, v0.w);
    __half2 h2 = __floats2half2_rn(v1.x, v1.y);
    __half2 h3 = __floats2half2_rn(v1.z, v1.w);
    *(uint4*)(g_encF + base) = make_uint4(h2u(h0), h2u(h1), h2u(h2), h2u(h3));
}

// ---------------------------------------------------------------------------
// K0b: W2 = attn_W[:, H:2H] -> fp16  [n][k] row-major
// ---------------------------------------------------------------------------
__global__ void cvt_w2_kernel(const float* __restrict__ W){
    size_t idx = ((size_t)blockIdx.x * 256 + threadIdx.x) * 8;
    int n = (int)(idx >> 10), k = (int)(idx & 1023);
    const float* src = W + (size_t)n * (2*NH) + NH + k;
    float4 v0 = *(const float4*)(src);
    float4 v1 = *(const float4*)(src + 4);
    __half2 h0 = __floats2half2_rn(v0.x, v0.y);
    __half2 h1 = __floats2half2_rn(v0.z, v0.w);
    __half2 h2 = __floats2half2_rn(v1.x, v1.y);
    __half2 h3 = __floats2half2_rn(v1.z, v1.w);
    *(uint4*)(g_w2F + idx) = make_uint4(h2u(h0), h2u(h1), h2u(h2), h2u(h3));
}

// ---------------------------------------------------------------------------
// K1: hidc[b][h] = hidden[b] . attn_W[h][0:H] + bias[h]   (fp32 exact)
// ---------------------------------------------------------------------------
__global__ void hidc_kernel(const float* __restrict__ hidden,
                            const float* __restrict__ W,
                            const float* __restrict__ bias){
    int idx = blockIdx.x * 256 + threadIdx.x;
    int b = idx >> 10, h = idx & 1023;
    const float4* hr = (const float4*)(hidden + (size_t)b * NH);
    const float4* wr = (const float4*)(W + (size_t)h * (2*NH));
    float acc = 0.f;
    #pragma unroll 4
    for (int k = 0; k < NH/4; k++){
        float4 a = hr[k], w = wr[k];
        acc += a.x*w.x + a.y*w.y + a.z*w.z + a.w*w.w;
    }
    g_hidc[idx] = acc + bias[h];
}

// ---------------------------------------------------------------------------
// K2: fp16 mma.sync GEMM + tanh + v-dot epilogue.
// CTA 128x256, 16 warps (2m x 8n), warp tile 64x32, k-chunk 64, 3-stage cp.async.
// grid (4 ntiles [x fastest -> A reuse in L2], 512 mtiles), 512 threads.
// ---------------------------------------------------------------------------
__global__ void __launch_bounds__(NTHREADS, 1)
gemm_scores_mma(const float* __restrict__ vW){
    extern __shared__ char smem[];
    const uint32_t sb = smem_u32(smem);
    float (*s_row)[8] = (float(*)[8])(smem + SROW_OFF);

    const int tid  = threadIdx.x;
    const int lane = tid & 31, wid = tid >> 5;
    const int wm = wid & 1, wn = wid >> 1;       // 2 x 8
    const int mbase = wm * 64, nbase = wn * 32;
    const int g = lane >> 2, t = lane & 3;
    const int ntile = blockIdx.x, mtile = blockIdx.y;
    const int m0 = mtile * M_CTA, n0 = ntile * N_CTA;

    const __half* Ag = g_encF + (size_t)m0 * NH;
    const __half* Bg = g_w2F + (size_t)n0 * NH;

    float c[4][4][4];
    #pragma unroll
    for (int i = 0; i < 4; i++)
        #pragma unroll
        for (int j = 0; j < 4; j++)
            #pragma unroll
            for (int k = 0; k < 4; k++) c[i][j][k] = 0.f;

    // per-thread swizzled base offsets (relative to stage base), ks folded via XOR
    const uint32_t r15 = (uint32_t)(lane & 15);
    const uint32_t c0  = ((uint32_t)lane >> 4) * 16;
    uint32_t relA[4], relB[2];
    #pragma unroll
    for (int mf = 0; mf < 4; mf++){
        uint32_t row = (uint32_t)mbase + mf * 16 + r15;
        relA[mf] = row * 128 + (c0 ^ ((row & 7) << 4));
    }
    #pragma unroll
    for (int nq = 0; nq < 2; nq++){
        uint32_t row = (uint32_t)nbase + nq * 16 + r15;
        relB[nq] = row * 128 + (c0 ^ ((row & 7) << 4));
    }

    // prefetch chunk ci into stage st
    auto prefetch = [&](int ci, int st){
        const uint32_t so = sb + st * STAGESZ;
        const int k0 = ci * KCH;
        // A: 128 rows x 8 x 16B units = 1024
        #pragma unroll
        for (int i = 0; i < 2; i++){
            int u = tid + i * NTHREADS;
            int row = u >> 3, cu = u & 7;
            uint32_t rel = (uint32_t)(row * 128) + (((uint32_t)cu * 16) ^ (((uint32_t)row & 7) << 4));
            cp16(so + rel, Ag + (size_t)row * NH + k0 + cu * 8);
        }
        // B: 256 rows x 8 x 16B units = 2048
        #pragma unroll
        for (int i = 0; i < 4; i++){
            int u = tid + i * NTHREADS;
            int row = u >> 3, cu = u & 7;
            uint32_t rel = (uint32_t)(row * 128) + (((uint32_t)cu * 16) ^ (((uint32_t)row & 7) << 4));
            cp16(so + SB_OFF + rel, Bg + (size_t)row * NH + k0 + cu * 8);
        }
    };

    prefetch(0, 0); cp_commit();
    prefetch(1, 1); cp_commit();
    prefetch(2, 2); cp_commit();

    for (int ci = 0; ci < NCHUNK; ci++){
        cp_wait<2>();
        __syncthreads();
        const int st = ci % NSTAGE;
        const uint32_t soA = sb + st * STAGESZ;
        const uint32_t soB = soA + SB_OFF;
        #pragma unroll
        for (int ks = 0; ks < 4; ks++){
            const uint32_t kx = (uint32_t)(ks << 5);
            uint32_t ah[4][4], bh[2][4];
            #pragma unroll
            for (int mf = 0; mf < 4; mf++)
                ldsm4(ah[mf], soA + (relA[mf] ^ kx));
            #pragma unroll
            for (int nq = 0; nq < 2; nq++)
                ldsm4(bh[nq], soB + (relB[nq] ^ kx));
            #pragma unroll
            for (int mf = 0; mf < 4; mf++){
                #pragma unroll
                for (int nf = 0; nf < 4; nf++){
                    const int nq = nf >> 1, hi = nf & 1;
                    mma16816(c[mf][nf], ah[mf], bh[nq][hi], bh[nq][hi+2]);
                }
            }
        }
        __syncthreads();
        if (ci + NSTAGE < NCHUNK) prefetch(ci + NSTAGE, st);
        cp_commit();
    }

    // Epilogue: partial scores over this CTA's 256 n-cols.
    float rs0[4] = {0,0,0,0}, rs1[4] = {0,0,0,0};
    #pragma unroll
    for (int mf = 0; mf < 4; mf++){
        const int mlo = mbase + mf*16 + g;
        const int blo = mlo & 31;
        const int bhi = (mlo + 8) & 31;
        #pragma unroll
        for (int nf = 0; nf < 4; nf++){
            const int ngl = n0 + nbase + nf*8 + 2*t;
            float v0 = __ldg(&vW[ngl]), v1 = __ldg(&vW[ngl+1]);
            float h00 = g_hidc[blo*NH + ngl], h01 = g_hidc[blo*NH + ngl + 1];
            float h10 = g_hidc[bhi*NH + ngl], h11 = g_hidc[bhi*NH + ngl + 1];
            rs0[mf] += tanhf(c[mf][nf][0] + h00) * v0 + tanhf(c[mf][nf][1] + h01) * v1;
            rs1[mf] += tanhf(c[mf][nf][2] + h10) * v0 + tanhf(c[mf][nf][3] + h11) * v1;
        }
    }
    #pragma unroll
    for (int mf = 0; mf < 4; mf++){
        rs0[mf] += __shfl_xor_sync(0xffffffffu, rs0[mf], 1);
        rs0[mf] += __shfl_xor_sync(0xffffffffu, rs0[mf], 2);
        rs1[mf] += __shfl_xor_sync(0xffffffffu, rs1[mf], 1);
        rs1[mf] += __shfl_xor_sync(0xffffffffu, rs1[mf], 2);
    }
    __syncthreads();
    if (t == 0){
        #pragma unroll
        for (int mf = 0; mf < 4; mf++){
            s_row[mbase + mf*16 + g    ][wn] = rs0[mf];
            s_row[mbase + mf*16 + g + 8][wn] = rs1[mf];
        }
    }
    __syncthreads();
    if (tid < 128){
        float s = 0.f;
        #pragma unroll
        for (int j = 0; j < 8; j++) s += s_row[tid][j];
        g_part[(size_t)ntile * MTOT + m0 + tid] = s;
    }
}

// ---------------------------------------------------------------------------
// K3: sum partials -> softmax over S per batch -> attn_weights; zero ctx
// ---------------------------------------------------------------------------
__global__ void softmax_kernel(float* __restrict__ w_out, float* __restrict__ ctx){
    __shared__ float sc[NS];
    __shared__ float red[256];
    const int b = blockIdx.x, tid = threadIdx.x;

    #pragma unroll
    for (int i = tid; i < NH; i += 256) ctx[b * NH + i] = 0.f;

    float lmax = -1e30f;
    for (int s = tid; s < NS; s += 256){
        float v = 0.f;
        #pragma unroll
        for (int nt = 0; nt < NTILES; nt++)
            v += g_part[(size_t)nt * MTOT + s * NB + b];
        sc[s] = v;
        lmax = fmaxf(lmax, v);
    }
    red[tid] = lmax; __syncthreads();
    for (int o = 128; o > 0; o >>= 1){
        if (tid < o) red[tid] = fmaxf(red[tid], red[tid + o]);
        __syncthreads();
    }
    const float mx = red[0];
    __syncthreads();

    float lsum = 0.f;
    for (int s = tid; s < NS; s += 256){
        float e = expf(sc[s] - mx);
        sc[s] = e;
        lsum += e;
    }
    red[tid] = lsum; __syncthreads();
    for (int o = 128; o > 0; o >>= 1){
        if (tid < o) red[tid] = red[tid] + red[tid + o];
        __syncthreads();
    }
    const float inv = 1.f / red[0];
    for (int s = tid; s < NS; s += 256)
        w_out[b * NS + s] = sc[s] * inv;
}

// ---------------------------------------------------------------------------
// K4: context[b][h] += sum_{s in chunk} w[b][s] * enc[s][b][h]  (atomic)
// ---------------------------------------------------------------------------
__global__ void context_kernel(const float* __restrict__ enc,
                               const float* __restrict__ w,
                               float* __restrict__ ctx){
    const int b = blockIdx.y;
    const int h = blockIdx.x * 128 + threadIdx.x;
    const int s0 = blockIdx.z * 128;
    const float* e  = enc + (size_t)s0 * (NB*NH) + (size_t)b * NH + h;
    const float* wb = w + (size_t)b * NS + s0;
    float acc = 0.f;
    #pragma unroll 8
    for (int j = 0; j < 128; j++)
        acc += wb[j] * e[(size_t)j * (NB*NH)];
    atomicAdd(&ctx[(size_t)b * NH + h], acc);
}

// ---------------------------------------------------------------------------
extern "C" void kernel_launch(void* const* d_in, const int* in_sizes, int n_in,
                              void* d_out, int out_size){
    const float* hidden = (const float*)d_in[0];   // [B,H]
    const float* enc    = (const float*)d_in[1];   // [S,B,H]
    const float* attn_W = (const float*)d_in[2];   // [H,2H]
    const float* attn_b = (const float*)d_in[3];   // [H]
    const float* v_W    = (const float*)d_in[4];   // [1,H]
    float* out = (float*)d_out;
    float* ctx = out;                 // [B,H]
    float* wts = out + NB*NH;         // [B,S]

    cudaFuncSetAttribute(gemm_scores_mma, cudaFuncAttributeMaxDynamicSharedMemorySize, SMEM_TOTAL);

    cvt_enc_kernel<<<(MTOT*(NH/8))/256, 256>>>(enc);
    cvt_w2_kernel<<<(NH*(NH/8))/256, 256>>>(attn_W);
    hidc_kernel<<<128, 256>>>(hidden, attn_W, attn_b);
    gemm_scores_mma<<<dim3(NTILES, MTOT/M_CTA), NTHREADS, SMEM_TOTAL>>>(v_W);
    softmax_kernel<<<NB, 256>>>(wts, ctx);
    context_kernel<<<dim3(NH/128, NB, NS/128), 128>>>(enc, wts, ctx);
}

// round 12
// speedup vs baseline: 1.1148x; 1.1148x over previous
#include <cuda_runtime.h>
#include <cuda_fp16.h>
#include <stdint.h>

#define NB 32
#define NS 2048
#define NH 1024
#define MTOT (NB*NS)      // 65536 flattened (s,b) rows
#define NTILES 4          // NH / N_CTA
#define N_CTA 256
#define M_CTA 128
#define KCH 64            // k-chunk elems (128B rows in fp16)
#define NCHUNK (NH/KCH)   // 16
#define NSTAGE 4
#define NTHREADS 256

// smem: per stage A 16KB + B 32KB
#define SB_OFF 16384
#define STAGESZ 49152
#define SROW_OFF (NSTAGE*STAGESZ)            // 196608
#define SMEM_TOTAL (NSTAGE*STAGESZ + 2048)   // 198656

// persistent scratch
__device__ float g_hidc[NB*NH];
__device__ float g_part[NTILES*MTOT];
__device__ __align__(16) __half g_encF[MTOT*NH];   // 134 MB
__device__ __align__(16) __half g_w2F[NH*NH];      // 2 MB

// ---------------- helpers ----------------
__device__ __forceinline__ uint32_t smem_u32(const void* p){
    uint32_t a;
    asm("{ .reg .u64 t; cvta.to.shared.u64 t, %1; cvt.u32.u64 %0, t; }" : "=r"(a) : "l"(p));
    return a;
}
__device__ __forceinline__ void cp16(uint32_t dst, const void* src){
    asm volatile("cp.async.cg.shared.global [%0], [%1], 16;" :: "r"(dst), "l"(src));
}
__device__ __forceinline__ void cp_commit(){
    asm volatile("cp.async.commit_group;");
}
template<int N> __device__ __forceinline__ void cp_wait(){
    asm volatile("cp.async.wait_group %0;" :: "n"(N));
}
__device__ __forceinline__ void ldsm4(uint32_t r[4], uint32_t addr){
    asm volatile("ldmatrix.sync.aligned.m8n8.x4.shared.b16 {%0,%1,%2,%3}, [%4];\n"
        : "=r"(r[0]),"=r"(r[1]),"=r"(r[2]),"=r"(r[3]) : "r"(addr));
}
__device__ __forceinline__ void mma16816(float c[4], const uint32_t a[4], uint32_t b0, uint32_t b1){
    asm volatile("mma.sync.aligned.m16n8k16.row.col.f32.f16.f16.f32 "
        "{%0,%1,%2,%3}, {%4,%5,%6,%7}, {%8,%9}, {%0,%1,%2,%3};\n"
        : "+f"(c[0]),"+f"(c[1]),"+f"(c[2]),"+f"(c[3])
        : "r"(a[0]),"r"(a[1]),"r"(a[2]),"r"(a[3]),"r"(b0),"r"(b1));
}
__device__ __forceinline__ float tanh_ap(float x){
    float y; asm("tanh.approx.f32 %0, %1;" : "=f"(y) : "f"(x)); return y;
}
__device__ __forceinline__ uint32_t h2u(__half2 v){ return *reinterpret_cast<uint32_t*>(&v); }

// ---------------------------------------------------------------------------
// K0a: enc fp32 -> fp16  (8 elems / thread)
// ---------------------------------------------------------------------------
__global__ void cvt_enc_kernel(const float* __restrict__ enc){
    size_t base = ((size_t)blockIdx.x * 256 + threadIdx.x) * 8;
    float4 v0 = *(const float4*)(enc + base);
    float4 v1 = *(const float4*)(enc + base + 4);
    __half2 h0 = __floats2half2_rn(v0.x, v0.y);
    __half2 h1 = __floats2half2_rn(v0.z, v0.w);
    __half2 h2 = __floats2half2_rn(v1.x, v1.y);
    __half2 h3 = __floats2half2_rn(v1.z, v1.w);
    *(uint4*)(g_encF + base) = make_uint4(h2u(h0), h2u(h1), h2u(h2), h2u(h3));
}

// ---------------------------------------------------------------------------
// K0b: W2 = attn_W[:, H:2H] -> fp16  [n][k] row-major
// ---------------------------------------------------------------------------
__global__ void cvt_w2_kernel(const float* __restrict__ W){
    size_t idx = ((size_t)blockIdx.x * 256 + threadIdx.x) * 8;
    int n = (int)(idx >> 10), k = (int)(idx & 1023);
    const float* src = W + (size_t)n * (2*NH) + NH + k;
    float4 v0 = *(const float4*)(src);
    float4 v1 = *(const float4*)(src + 4);
    __half2 h0 = __floats2half2_rn(v0.x, v0.y);
    __half2 h1 = __floats2half2_rn(v0.z, v0.w);
    __half2 h2 = __floats2half2_rn(v1.x, v1.y);
    __half2 h3 = __floats2half2_rn(v1.z, v1.w);
    *(uint4*)(g_w2F + idx) = make_uint4(h2u(h0), h2u(h1), h2u(h2), h2u(h3));
}

// ---------------------------------------------------------------------------
// K1: hidc[b][h] = hidden[b] . attn_W[h][0:H] + bias[h]   (fp32 exact)
// ---------------------------------------------------------------------------
__global__ void hidc_kernel(const float* __restrict__ hidden,
                            const float* __restrict__ W,
                            const float* __restrict__ bias){
    int idx = blockIdx.x * 256 + threadIdx.x;
    int b = idx >> 10, h = idx & 1023;
    const float4* hr = (const float4*)(hidden + (size_t)b * NH);
    const float4* wr = (const float4*)(W + (size_t)h * (2*NH));
    float acc = 0.f;
    #pragma unroll 4
    for (int k = 0; k < NH/4; k++){
        float4 a = hr[k], w = wr[k];
        acc += a.x*w.x + a.y*w.y + a.z*w.z + a.w*w.w;
    }
    g_hidc[idx] = acc + bias[h];
}

// ---------------------------------------------------------------------------
// K2: fp16 mma.sync GEMM + tanh + v-dot epilogue.
// CTA 128x256, 8 warps (2m x 4n), warp tile 64x64, k-chunk 64,
// 4-stage cp.async pipeline, one barrier per chunk, prefetch-early.
// grid (4 ntiles [x fastest -> A reuse in L2], 512 mtiles), 256 threads.
// ---------------------------------------------------------------------------
__global__ void __launch_bounds__(NTHREADS, 1)
gemm_scores_mma(const float* __restrict__ vW){
    extern __shared__ char smem[];
    const uint32_t sb = smem_u32(smem);
    float (*s_row)[4] = (float(*)[4])(smem + SROW_OFF);

    const int tid  = threadIdx.x;
    const int lane = tid & 31, wid = tid >> 5;
    const int wm = wid & 1, wn = wid >> 1;       // 2 x 4
    const int mbase = wm * 64, nbase = wn * 64;
    const int g = lane >> 2, t = lane & 3;
    const int ntile = blockIdx.x, mtile = blockIdx.y;
    const int m0 = mtile * M_CTA, n0 = ntile * N_CTA;

    const __half* Ag = g_encF + (size_t)m0 * NH;
    const __half* Bg = g_w2F + (size_t)n0 * NH;

    float c[4][8][4];
    #pragma unroll
    for (int i = 0; i < 4; i++)
        #pragma unroll
        for (int j = 0; j < 8; j++)
            #pragma unroll
            for (int k = 0; k < 4; k++) c[i][j][k] = 0.f;

    // ldsm base offsets (swizzled); ks folded via XOR with ks<<5
    const uint32_t r15 = (uint32_t)(lane & 15);
    const uint32_t c0  = ((uint32_t)lane >> 4) * 16;
    uint32_t relA[4], relB[4];
    #pragma unroll
    for (int mf = 0; mf < 4; mf++){
        uint32_t row = (uint32_t)mbase + mf * 16 + r15;
        relA[mf] = row * 128 + (c0 ^ ((row & 7) << 4));
    }
    #pragma unroll
    for (int nq = 0; nq < 4; nq++){
        uint32_t row = (uint32_t)nbase + nq * 16 + r15;
        relB[nq] = row * 128 + (c0 ^ ((row & 7) << 4));
    }

    // cp.async bases: rows advance by 32 per i -> +32*NH global, +4096B smem
    // (swizzle invariant: row & 7 unchanged under row += 32)
    const int row0 = tid >> 3, cu0 = tid & 7;
    const uint32_t cprel = (uint32_t)(row0 * 128) + (((uint32_t)cu0 * 16) ^ (((uint32_t)row0 & 7) << 4));
    const size_t go0 = (size_t)row0 * NH + cu0 * 8;

    auto prefetch = [&](int ci, int st){
        const uint32_t so = sb + st * STAGESZ;
        const __half* pa = Ag + go0 + ci * KCH;
        const __half* pb = Bg + go0 + ci * KCH;
        #pragma unroll
        for (int i = 0; i < 4; i++)
            cp16(so + cprel + i * 4096, pa + (size_t)i * (32 * NH));
        #pragma unroll
        for (int i = 0; i < 8; i++)
            cp16(so + SB_OFF + cprel + i * 4096, pb + (size_t)i * (32 * NH));
    };

    prefetch(0, 0); cp_commit();
    prefetch(1, 1); cp_commit();
    prefetch(2, 2); cp_commit();

    for (int ci = 0; ci < NCHUNK; ci++){
        cp_wait<2>();
        __syncthreads();
        // prefetch chunk ci+3 into stage (ci+3)&3 (freed at iter ci-1), overlapping mma
        if (ci + 3 < NCHUNK) prefetch(ci + 3, (ci + 3) & 3);
        cp_commit();

        const uint32_t soA = sb + (ci & 3) * STAGESZ;
        const uint32_t soB = soA + SB_OFF;
        #pragma unroll
        for (int ks = 0; ks < 4; ks++){
            const uint32_t kx = (uint32_t)(ks << 5);
            uint32_t ah[4][4], bh[4][4];
            #pragma unroll
            for (int nq = 0; nq < 4; nq++)
                ldsm4(bh[nq], soB + (relB[nq] ^ kx));
            #pragma unroll
            for (int mf = 0; mf < 4; mf++)
                ldsm4(ah[mf], soA + (relA[mf] ^ kx));
            #pragma unroll
            for (int mf = 0; mf < 4; mf++){
                #pragma unroll
                for (int nf = 0; nf < 8; nf++){
                    const int nq = nf >> 1, hi = nf & 1;
                    mma16816(c[mf][nf], ah[mf], bh[nq][hi], bh[nq][hi+2]);
                }
            }
        }
    }

    // Epilogue: partial scores over this CTA's 256 n-cols (tanh.approx).
    float rs0[4] = {0,0,0,0}, rs1[4] = {0,0,0,0};
    #pragma unroll
    for (int mf = 0; mf < 4; mf++){
        const int mlo = mbase + mf*16 + g;
        const int blo = mlo & 31;
        const int bhi = (mlo + 8) & 31;
        #pragma unroll
        for (int nf = 0; nf < 8; nf++){
            const int ngl = n0 + nbase + nf*8 + 2*t;
            float v0 = __ldg(&vW[ngl]), v1 = __ldg(&vW[ngl+1]);
            float h00 = g_hidc[blo*NH + ngl], h01 = g_hidc[blo*NH + ngl + 1];
            float h10 = g_hidc[bhi*NH + ngl], h11 = g_hidc[bhi*NH + ngl + 1];
            rs0[mf] += tanh_ap(c[mf][nf][0] + h00) * v0 + tanh_ap(c[mf][nf][1] + h01) * v1;
            rs1[mf] += tanh_ap(c[mf][nf][2] + h10) * v0 + tanh_ap(c[mf][nf][3] + h11) * v1;
        }
    }
    #pragma unroll
    for (int mf = 0; mf < 4; mf++){
        rs0[mf] += __shfl_xor_sync(0xffffffffu, rs0[mf], 1);
        rs0[mf] += __shfl_xor_sync(0xffffffffu, rs0[mf], 2);
        rs1[mf] += __shfl_xor_sync(0xffffffffu, rs1[mf], 1);
        rs1[mf] += __shfl_xor_sync(0xffffffffu, rs1[mf], 2);
    }
    __syncthreads();
    if (t == 0){
        #pragma unroll
        for (int mf = 0; mf < 4; mf++){
            s_row[mbase + mf*16 + g    ][wn] = rs0[mf];
            s_row[mbase + mf*16 + g + 8][wn] = rs1[mf];
        }
    }
    __syncthreads();
    if (tid < 128){
        float s = s_row[tid][0] + s_row[tid][1] + s_row[tid][2] + s_row[tid][3];
        g_part[(size_t)ntile * MTOT + m0 + tid] = s;
    }
}

// ---------------------------------------------------------------------------
// K3: sum partials -> softmax over S per batch -> attn_weights; zero ctx
// ---------------------------------------------------------------------------
__global__ void softmax_kernel(float* __restrict__ w_out, float* __restrict__ ctx){
    __shared__ float sc[NS];
    __shared__ float red[256];
    const int b = blockIdx.x, tid = threadIdx.x;

    #pragma unroll
    for (int i = tid; i < NH; i += 256) ctx[b * NH + i] = 0.f;

    float lmax = -1e30f;
    for (int s = tid; s < NS; s += 256){
        float v = 0.f;
        #pragma unroll
        for (int nt = 0; nt < NTILES; nt++)
            v += g_part[(size_t)nt * MTOT + s * NB + b];
        sc[s] = v;
        lmax = fmaxf(lmax, v);
    }
    red[tid] = lmax; __syncthreads();
    for (int o = 128; o > 0; o >>= 1){
        if (tid < o) red[tid] = fmaxf(red[tid], red[tid + o]);
        __syncthreads();
    }
    const float mx = red[0];
    __syncthreads();

    float lsum = 0.f;
    for (int s = tid; s < NS; s += 256){
        float e = expf(sc[s] - mx);
        sc[s] = e;
        lsum += e;
    }
    red[tid] = lsum; __syncthreads();
    for (int o = 128; o > 0; o >>= 1){
        if (tid < o) red[tid] = red[tid] + red[tid + o];
        __syncthreads();
    }
    const float inv = 1.f / red[0];
    for (int s = tid; s < NS; s += 256)
        w_out[b * NS + s] = sc[s] * inv;
}

// ---------------------------------------------------------------------------
// K4: context[b][h] += sum_{s in chunk} w[b][s] * enc_fp16[s][b][h]  (atomic)
// grid (NH/256, NB, NS/128), 128 threads; each thread handles 2 h via half2
// ---------------------------------------------------------------------------
__global__ void context_kernel(const float* __restrict__ w,
                               float* __restrict__ ctx){
    const int b = blockIdx.y;
    const int h = blockIdx.x * 256 + threadIdx.x * 2;
    const int s0 = blockIdx.z * 128;
    const __half2* e = (const __half2*)(g_encF + (size_t)s0 * (NB*NH) + (size_t)b * NH + h);
    const float* wb = w + (size_t)b * NS + s0;
    const size_t stride2 = (NB*NH) / 2;
    float ax = 0.f, ay = 0.f;
    #pragma unroll 8
    for (int j = 0; j < 128; j++){
        float2 f = __half22float2(e[(size_t)j * stride2]);
        float wv = wb[j];
        ax += wv * f.x;
        ay += wv * f.y;
    }
    atomicAdd(&ctx[(size_t)b * NH + h], ax);
    atomicAdd(&ctx[(size_t)b * NH + h + 1], ay);
}

// ---------------------------------------------------------------------------
extern "C" void kernel_launch(void* const* d_in, const int* in_sizes, int n_in,
                              void* d_out, int out_size){
    const float* hidden = (const float*)d_in[0];   // [B,H]
    const float* enc    = (const float*)d_in[1];   // [S,B,H]
    const float* attn_W = (const float*)d_in[2];   // [H,2H]
    const float* attn_b = (const float*)d_in[3];   // [H]
    const float* v_W    = (const float*)d_in[4];   // [1,H]
    float* out = (float*)d_out;
    float* ctx = out;                 // [B,H]
    float* wts = out + NB*NH;         // [B,S]

    cudaFuncSetAttribute(gemm_scores_mma, cudaFuncAttributeMaxDynamicSharedMemorySize, SMEM_TOTAL);

    cvt_enc_kernel<<<(MTOT*(NH/8))/256, 256>>>(enc);
    cvt_w2_kernel<<<(NH*(NH/8))/256, 256>>>(attn_W);
    hidc_kernel<<<128, 256>>>(hidden, attn_W, attn_b);
    gemm_scores_mma<<<dim3(NTILES, MTOT/M_CTA), NTHREADS, SMEM_TOTAL>>>(v_W);
    softmax_kernel<<<NB, 256>>>(wts, ctx);
    context_kernel<<<dim3(NH/256, NB, NS/128), 128>>>(wts, ctx);
}

// round 15
// speedup vs baseline: 1.2041x; 1.0801x over previous
#include <cuda_runtime.h>
#include <cuda_fp16.h>
#include <stdint.h>

#define NB 32
#define NS 2048
#define NH 1024
#define MTOT (NB*NS)      // 65536 flattened (s,b) rows
#define NTILES 4          // NH / N_CTA
#define N_CTA 256
#define M_CTA 128
#define KCH 64            // k-chunk elems (128B rows in fp16)
#define NCHUNK (NH/KCH)   // 16
#define NSTAGE 4
#define NTHREADS 256

// smem: per stage A 16KB + B 32KB
#define SB_OFF 16384
#define STAGESZ 49152
#define SROW_OFF (NSTAGE*STAGESZ)            // 196608
#define SMEM_TOTAL (NSTAGE*STAGESZ + 2048)   // 198656

// persistent scratch
__device__ float g_hidc[NB*NH];
__device__ float g_part[NTILES*MTOT];
__device__ __align__(16) __half g_encF[MTOT*NH];   // 134 MB
__device__ __align__(16) __half g_w2F[NH*NH];      // 2 MB

// ---------------- helpers ----------------
__device__ __forceinline__ uint32_t smem_u32(const void* p){
    uint32_t a;
    asm("{ .reg .u64 t; cvta.to.shared.u64 t, %1; cvt.u32.u64 %0, t; }" : "=r"(a) : "l"(p));
    return a;
}
__device__ __forceinline__ void cp16(uint32_t dst, const void* src){
    asm volatile("cp.async.cg.shared.global [%0], [%1], 16;" :: "r"(dst), "l"(src));
}
__device__ __forceinline__ void cp_commit(){
    asm volatile("cp.async.commit_group;");
}
template<int N> __device__ __forceinline__ void cp_wait(){
    asm volatile("cp.async.wait_group %0;" :: "n"(N));
}
__device__ __forceinline__ void ldsm4(uint32_t r[4], uint32_t addr){
    asm volatile("ldmatrix.sync.aligned.m8n8.x4.shared.b16 {%0,%1,%2,%3}, [%4];\n"
        : "=r"(r[0]),"=r"(r[1]),"=r"(r[2]),"=r"(r[3]) : "r"(addr));
}
__device__ __forceinline__ void mma16816(float c[4], const uint32_t a[4], uint32_t b0, uint32_t b1){
    asm volatile("mma.sync.aligned.m16n8k16.row.col.f32.f16.f16.f32 "
        "{%0,%1,%2,%3}, {%4,%5,%6,%7}, {%8,%9}, {%0,%1,%2,%3};\n"
        : "+f"(c[0]),"+f"(c[1]),"+f"(c[2]),"+f"(c[3])
        : "r"(a[0]),"r"(a[1]),"r"(a[2]),"r"(a[3]),"r"(b0),"r"(b1));
}
__device__ __forceinline__ float tanh_ap(float x){
    float y; asm("tanh.approx.f32 %0, %1;" : "=f"(y) : "f"(x)); return y;
}
__device__ __forceinline__ uint32_t h2u(__half2 v){ return *reinterpret_cast<uint32_t*>(&v); }

// ---------------------------------------------------------------------------
// K0a: enc fp32 -> fp16  (8 elems / thread)
// ---------------------------------------------------------------------------
__global__ void cvt_enc_kernel(const float* __restrict__ enc){
    size_t base = ((size_t)blockIdx.x * 256 + threadIdx.x) * 8;
    float4 v0 = *(const float4*)(enc + base);
    float4 v1 = *(const float4*)(enc + base + 4);
    __half2 h0 = __floats2half2_rn(v0.x, v0.y);
    __half2 h1 = __floats2half2_rn(v0.z, v0.w);
    __half2 h2 = __floats2half2_rn(v1.x, v1.y);
    __half2 h3 = __floats2half2_rn(v1.z, v1.w);
    *(uint4*)(g_encF + base) = make_uint4(h2u(h0), h2u(h1), h2u(h2), h2u(h3));
}

// ---------------------------------------------------------------------------
// K0b: W2 = attn_W[:, H:2H] -> fp16  [n][k] row-major
// ---------------------------------------------------------------------------
__global__ void cvt_w2_kernel(const float* __restrict__ W){
    size_t idx = ((size_t)blockIdx.x * 256 + threadIdx.x) * 8;
    int n = (int)(idx >> 10), k = (int)(idx & 1023);
    const float* src = W + (size_t)n * (2*NH) + NH + k;
    float4 v0 = *(const float4*)(src);
    float4 v1 = *(const float4*)(src + 4);
    __half2 h0 = __floats2half2_rn(v0.x, v0.y);
    __half2 h1 = __floats2half2_rn(v0.z, v0.w);
    __half2 h2 = __floats2half2_rn(v1.x, v1.y);
    __half2 h3 = __floats2half2_rn(v1.z, v1.w);
    *(uint4*)(g_w2F + idx) = make_uint4(h2u(h0), h2u(h1), h2u(h2), h2u(h3));
}

// ---------------------------------------------------------------------------
// K1: hidc[b][h] = hidden[b] . attn_W[h][0:H] + bias[h]   (fp32 exact)
// ---------------------------------------------------------------------------
__global__ void hidc_kernel(const float* __restrict__ hidden,
                            const float* __restrict__ W,
                            const float* __restrict__ bias){
    int idx = blockIdx.x * 256 + threadIdx.x;
    int b = idx >> 10, h = idx & 1023;
    const float4* hr = (const float4*)(hidden + (size_t)b * NH);
    const float4* wr = (const float4*)(W + (size_t)h * (2*NH));
    float acc = 0.f;
    #pragma unroll 4
    for (int k = 0; k < NH/4; k++){
        float4 a = hr[k], w = wr[k];
        acc += a.x*w.x + a.y*w.y + a.z*w.z + a.w*w.w;
    }
    g_hidc[idx] = acc + bias[h];
}

// ---------------------------------------------------------------------------
// K2: fp16 mma.sync GEMM + tanh + v-dot epilogue.
// CTA 128x256, 8 warps (2m x 4n), warp tile 64x64, k-chunk 64,
// 4-stage cp.async pipeline + ks-level fragment double buffering.
// Slot rule: fragments for k-step ks live in slot (ks & 1), every chunk.
// grid (4 ntiles [x fastest -> A reuse in L2], 512 mtiles), 256 threads.
// ---------------------------------------------------------------------------
__global__ void __launch_bounds__(NTHREADS, 1)
gemm_scores_mma(const float* __restrict__ vW){
    extern __shared__ char smem[];
    const uint32_t sb = smem_u32(smem);
    float (*s_row)[4] = (float(*)[4])(smem + SROW_OFF);

    const int tid  = threadIdx.x;
    const int lane = tid & 31, wid = tid >> 5;
    const int wm = wid & 1, wn = wid >> 1;       // 2 x 4
    const int mbase = wm * 64, nbase = wn * 64;
    const int g = lane >> 2, t = lane & 3;
    const int ntile = blockIdx.x, mtile = blockIdx.y;
    const int m0 = mtile * M_CTA, n0 = ntile * N_CTA;

    const __half* Ag = g_encF + (size_t)m0 * NH;
    const __half* Bg = g_w2F + (size_t)n0 * NH;

    float c[4][8][4];
    #pragma unroll
    for (int i = 0; i < 4; i++)
        #pragma unroll
        for (int j = 0; j < 8; j++)
            #pragma unroll
            for (int k = 0; k < 4; k++) c[i][j][k] = 0.f;

    // ldsm base offsets (swizzled); ks folded via XOR with ks<<5
    const uint32_t r15 = (uint32_t)(lane & 15);
    const uint32_t c0  = ((uint32_t)lane >> 4) * 16;
    uint32_t relA[4], relB[4];
    #pragma unroll
    for (int mf = 0; mf < 4; mf++){
        uint32_t row = (uint32_t)mbase + mf * 16 + r15;
        relA[mf] = row * 128 + (c0 ^ ((row & 7) << 4));
    }
    #pragma unroll
    for (int nq = 0; nq < 4; nq++){
        uint32_t row = (uint32_t)nbase + nq * 16 + r15;
        relB[nq] = row * 128 + (c0 ^ ((row & 7) << 4));
    }

    // cp.async bases: rows advance by 32 per i -> +32*NH global, +4096B smem
    const int row0 = tid >> 3, cu0 = tid & 7;
    const uint32_t cprel = (uint32_t)(row0 * 128) + (((uint32_t)cu0 * 16) ^ (((uint32_t)row0 & 7) << 4));
    const size_t go0 = (size_t)row0 * NH + cu0 * 8;

    auto prefetch = [&](int ci, int st){
        const uint32_t so = sb + st * STAGESZ;
        const __half* pa = Ag + go0 + ci * KCH;
        const __half* pb = Bg + go0 + ci * KCH;
        #pragma unroll
        for (int i = 0; i < 4; i++)
            cp16(so + cprel + i * 4096, pa + (size_t)i * (32 * NH));
        #pragma unroll
        for (int i = 0; i < 8; i++)
            cp16(so + SB_OFF + cprel + i * 4096, pb + (size_t)i * (32 * NH));
    };

    // fragment double buffer: slot = ks & 1
    uint32_t ah[2][4][4], bh[2][4][4];

    auto load_frags = [&](int slot, uint32_t soA, int ks){
        const uint32_t soB = soA + SB_OFF;
        const uint32_t kx = (uint32_t)(ks << 5);
        #pragma unroll
        for (int nq = 0; nq < 4; nq++)
            ldsm4(bh[slot][nq], soB + (relB[nq] ^ kx));
        #pragma unroll
        for (int mf = 0; mf < 4; mf++)
            ldsm4(ah[slot][mf], soA + (relA[mf] ^ kx));
    };
    auto do_mma = [&](int slot){
        #pragma unroll
        for (int mf = 0; mf < 4; mf++){
            #pragma unroll
            for (int nf = 0; nf < 8; nf++){
                const int nq = nf >> 1, hi = nf & 1;
                mma16816(c[mf][nf], ah[slot][mf], bh[slot][nq][hi], bh[slot][nq][hi+2]);
            }
        }
    };

    prefetch(0, 0); cp_commit();
    prefetch(1, 1); cp_commit();
    prefetch(2, 2); cp_commit();

    cp_wait<2>();
    __syncthreads();
    load_frags(0, sb /*stage 0*/, 0);           // ks0 -> slot 0

    for (int ci = 0; ci < NCHUNK; ci++){
        // stage (ci+3)&3 == (ci-1)&3: all smem reads of it finished before the
        // sync in the previous iteration (ks3 mma reads registers only)
        if (ci + 3 < NCHUNK) prefetch(ci + 3, (ci + 3) & 3);
        cp_commit();

        const uint32_t soA = sb + (ci & 3) * STAGESZ;

        load_frags(1, soA, 1);  do_mma(0);      // ks1 -> s1 | mma ks0 (s0)
        load_frags(0, soA, 2);  do_mma(1);      // ks2 -> s0 | mma ks1 (s1)
        load_frags(1, soA, 3);  do_mma(0);      // ks3 -> s1 | mma ks2 (s0)

        if (ci + 1 < NCHUNK){
            cp_wait<2>();                       // group ci+1 complete
            __syncthreads();
            load_frags(0, sb + ((ci + 1) & 3) * STAGESZ, 0);   // next ks0 -> s0
        }
        do_mma(1);                              // mma ks3 (s1)
    }

    // Epilogue: partial scores over this CTA's 256 n-cols (tanh.approx).
    float rs0[4] = {0,0,0,0}, rs1[4] = {0,0,0,0};
    #pragma unroll
    for (int mf = 0; mf < 4; mf++){
        const int mlo = mbase + mf*16 + g;
        const int blo = mlo & 31;
        const int bhi = (mlo + 8) & 31;
        #pragma unroll
        for (int nf = 0; nf < 8; nf++){
            const int ngl = n0 + nbase + nf*8 + 2*t;
            float v0 = __ldg(&vW[ngl]), v1 = __ldg(&vW[ngl+1]);
            float h00 = g_hidc[blo*NH + ngl], h01 = g_hidc[blo*NH + ngl + 1];
            float h10 = g_hidc[bhi*NH + ngl], h11 = g_hidc[bhi*NH + ngl + 1];
            rs0[mf] += tanh_ap(c[mf][nf][0] + h00) * v0 + tanh_ap(c[mf][nf][1] + h01) * v1;
            rs1[mf] += tanh_ap(c[mf][nf][2] + h10) * v0 + tanh_ap(c[mf][nf][3] + h11) * v1;
        }
    }
    #pragma unroll
    for (int mf = 0; mf < 4; mf++){
        rs0[mf] += __shfl_xor_sync(0xffffffffu, rs0[mf], 1);
        rs0[mf] += __shfl_xor_sync(0xffffffffu, rs0[mf], 2);
        rs1[mf] += __shfl_xor_sync(0xffffffffu, rs1[mf], 1);
        rs1[mf] += __shfl_xor_sync(0xffffffffu, rs1[mf], 2);
    }
    __syncthreads();
    if (t == 0){
        #pragma unroll
        for (int mf = 0; mf < 4; mf++){
            s_row[mbase + mf*16 + g    ][wn] = rs0[mf];
            s_row[mbase + mf*16 + g + 8][wn] = rs1[mf];
        }
    }
    __syncthreads();
    if (tid < 128){
        float s = s_row[tid][0] + s_row[tid][1] + s_row[tid][2] + s_row[tid][3];
        g_part[(size_t)ntile * MTOT + m0 + tid] = s;
    }
}

// ---------------------------------------------------------------------------
// K3: sum partials -> softmax over S per batch -> attn_weights; zero ctx
// ---------------------------------------------------------------------------
__global__ void softmax_kernel(float* __restrict__ w_out, float* __restrict__ ctx){
    __shared__ float sc[NS];
    __shared__ float red[256];
    const int b = blockIdx.x, tid = threadIdx.x;

    #pragma unroll
    for (int i = tid; i < NH; i += 256) ctx[b * NH + i] = 0.f;

    float lmax = -1e30f;
    for (int s = tid; s < NS; s += 256){
        float v = 0.f;
        #pragma unroll
        for (int nt = 0; nt < NTILES; nt++)
            v += g_part[(size_t)nt * MTOT + s * NB + b];
        sc[s] = v;
        lmax = fmaxf(lmax, v);
    }
    red[tid] = lmax; __syncthreads();
    for (int o = 128; o > 0; o >>= 1){
        if (tid < o) red[tid] = fmaxf(red[tid], red[tid + o]);
        __syncthreads();
    }
    const float mx = red[0];
    __syncthreads();

    float lsum = 0.f;
    for (int s = tid; s < NS; s += 256){
        float e = expf(sc[s] - mx);
        sc[s] = e;
        lsum += e;
    }
    red[tid] = lsum; __syncthreads();
    for (int o = 128; o > 0; o >>= 1){
        if (tid < o) red[tid] = red[tid] + red[tid + o];
        __syncthreads();
    }
    const float inv = 1.f / red[0];
    for (int s = tid; s < NS; s += 256)
        w_out[b * NS + s] = sc[s] * inv;
}

// ---------------------------------------------------------------------------
// K4: context[b][h] += sum_{s in chunk} w[b][s] * enc_fp16[s][b][h]  (atomic)
// ---------------------------------------------------------------------------
__global__ void context_kernel(const float* __restrict__ w,
                               float* __restrict__ ctx){
    const int b = blockIdx.y;
    const int h = blockIdx.x * 256 + threadIdx.x * 2;
    const int s0 = blockIdx.z * 128;
    const __half2* e = (const __half2*)(g_encF + (size_t)s0 * (NB*NH) + (size_t)b * NH + h);
    const float* wb = w + (size_t)b * NS + s0;
    const size_t stride2 = (NB*NH) / 2;
    float ax = 0.f, ay = 0.f;
    #pragma unroll 8
    for (int j = 0; j < 128; j++){
        float2 f = __half22float2(e[(size_t)j * stride2]);
        float wv = wb[j];
        ax += wv * f.x;
        ay += wv * f.y;
    }
    atomicAdd(&ctx[(size_t)b * NH + h], ax);
    atomicAdd(&ctx[(size_t)b * NH + h + 1], ay);
}

// ---------------------------------------------------------------------------
extern "C" void kernel_launch(void* const* d_in, const int* in_sizes, int n_in,
                              void* d_out, int out_size){
    const float* hidden = (const float*)d_in[0];   // [B,H]
    const float* enc    = (const float*)d_in[1];   // [S,B,H]
    const float* attn_W = (const float*)d_in[2];   // [H,2H]
    const float* attn_b = (const float*)d_in[3];   // [H]
    const float* v_W    = (const float*)d_in[4];   // [1,H]
    float* out = (float*)d_out;
    float* ctx = out;                 // [B,H]
    float* wts = out + NB*NH;         // [B,S]

    cudaFuncSetAttribute(gemm_scores_mma, cudaFuncAttributeMaxDynamicSharedMemorySize, SMEM_TOTAL);

    cvt_enc_kernel<<<(MTOT*(NH/8))/256, 256>>>(enc);
    cvt_w2_kernel<<<(NH*(NH/8))/256, 256>>>(attn_W);
    hidc_kernel<<<128, 256>>>(hidden, attn_W, attn_b);
    gemm_scores_mma<<<dim3(NTILES, MTOT/M_CTA), NTHREADS, SMEM_TOTAL>>>(v_W);
    softmax_kernel<<<NB, 256>>>(wts, ctx);
    context_kernel<<<dim3(NH/256, NB, NS/128), 128>>>(wts, ctx);
}

// round 16
// speedup vs baseline: 1.3310x; 1.1054x over previous
#include <cuda_runtime.h>
#include <cuda_fp16.h>
#include <stdint.h>

#define NB 32
#define NS 2048
#define NH 1024
#define MTOT (NB*NS)      // 65536 flattened (s,b) rows
#define NTILES 8          // NH / N_CTA
#define N_CTA 128
#define M_CTA 128
#define KCH 64            // k-chunk elems (128B rows in fp16)
#define NCHUNK (NH/KCH)   // 16
#define NSTAGE 3
#define NTHREADS 128

// smem per stage: A 16KB + B 16KB
#define SB_OFF 16384
#define STAGESZ 32768
#define SROW_OFF (NSTAGE*STAGESZ)            // 98304
#define SMEM_TOTAL (NSTAGE*STAGESZ + 1024)   // 99328  (x2 CTAs = 198656 <= 228KB)

// persistent scratch
__device__ float g_hidc[NB*NH];
__device__ float g_part[NTILES*MTOT];
__device__ __align__(16) __half g_encF[MTOT*NH];   // 134 MB
__device__ __align__(16) __half g_w2F[NH*NH];      // 2 MB

// ---------------- helpers ----------------
__device__ __forceinline__ uint32_t smem_u32(const void* p){
    uint32_t a;
    asm("{ .reg .u64 t; cvta.to.shared.u64 t, %1; cvt.u32.u64 %0, t; }" : "=r"(a) : "l"(p));
    return a;
}
__device__ __forceinline__ void cp16(uint32_t dst, const void* src){
    asm volatile("cp.async.cg.shared.global [%0], [%1], 16;" :: "r"(dst), "l"(src));
}
__device__ __forceinline__ void cp_commit(){
    asm volatile("cp.async.commit_group;");
}
template<int N> __device__ __forceinline__ void cp_wait(){
    asm volatile("cp.async.wait_group %0;" :: "n"(N));
}
__device__ __forceinline__ void ldsm4(uint32_t r[4], uint32_t addr){
    asm volatile("ldmatrix.sync.aligned.m8n8.x4.shared.b16 {%0,%1,%2,%3}, [%4];\n"
        : "=r"(r[0]),"=r"(r[1]),"=r"(r[2]),"=r"(r[3]) : "r"(addr));
}
__device__ __forceinline__ void mma16816(float c[4], const uint32_t a[4], uint32_t b0, uint32_t b1){
    asm volatile("mma.sync.aligned.m16n8k16.row.col.f32.f16.f16.f32 "
        "{%0,%1,%2,%3}, {%4,%5,%6,%7}, {%8,%9}, {%0,%1,%2,%3};\n"
        : "+f"(c[0]),"+f"(c[1]),"+f"(c[2]),"+f"(c[3])
        : "r"(a[0]),"r"(a[1]),"r"(a[2]),"r"(a[3]),"r"(b0),"r"(b1));
}
__device__ __forceinline__ float tanh_ap(float x){
    float y; asm("tanh.approx.f32 %0, %1;" : "=f"(y) : "f"(x)); return y;
}
__device__ __forceinline__ uint32_t h2u(__half2 v){ return *reinterpret_cast<uint32_t*>(&v); }

// ---------------------------------------------------------------------------
// K0a: enc fp32 -> fp16  (8 elems / thread)
// ---------------------------------------------------------------------------
__global__ void cvt_enc_kernel(const float* __restrict__ enc){
    size_t base = ((size_t)blockIdx.x * 256 + threadIdx.x) * 8;
    float4 v0 = *(const float4*)(enc + base);
    float4 v1 = *(const float4*)(enc + base + 4);
    __half2 h0 = __floats2half2_rn(v0.x, v0.y);
    __half2 h1 = __floats2half2_rn(v0.z, v0.w);
    __half2 h2 = __floats2half2_rn(v1.x, v1.y);
    __half2 h3 = __floats2half2_rn(v1.z, v1.w);
    *(uint4*)(g_encF + base) = make_uint4(h2u(h0), h2u(h1), h2u(h2), h2u(h3));
}

// ---------------------------------------------------------------------------
// K0b: W2 = attn_W[:, H:2H] -> fp16  [n][k] row-major
// ---------------------------------------------------------------------------
__global__ void cvt_w2_kernel(const float* __restrict__ W){
    size_t idx = ((size_t)blockIdx.x * 256 + threadIdx.x) * 8;
    int n = (int)(idx >> 10), k = (int)(idx & 1023);
    const float* src = W + (size_t)n * (2*NH) + NH + k;
    float4 v0 = *(const float4*)(src);
    float4 v1 = *(const float4*)(src + 4);
    __half2 h0 = __floats2half2_rn(v0.x, v0.y);
    __half2 h1 = __floats2half2_rn(v0.z, v0.w);
    __half2 h2 = __floats2half2_rn(v1.x, v1.y);
    __half2 h3 = __floats2half2_rn(v1.z, v1.w);
    *(uint4*)(g_w2F + idx) = make_uint4(h2u(h0), h2u(h1), h2u(h2), h2u(h3));
}

// ---------------------------------------------------------------------------
// K1: hidc[b][h] = hidden[b] . attn_W[h][0:H] + bias[h]   (fp32 exact)
// ---------------------------------------------------------------------------
__global__ void hidc_kernel(const float* __restrict__ hidden,
                            const float* __restrict__ W,
                            const float* __restrict__ bias){
    int idx = blockIdx.x * 256 + threadIdx.x;
    int b = idx >> 10, h = idx & 1023;
    const float4* hr = (const float4*)(hidden + (size_t)b * NH);
    const float4* wr = (const float4*)(W + (size_t)h * (2*NH));
    float acc = 0.f;
    #pragma unroll 4
    for (int k = 0; k < NH/4; k++){
        float4 a = hr[k], w = wr[k];
        acc += a.x*w.x + a.y*w.y + a.z*w.z + a.w*w.w;
    }
    g_hidc[idx] = acc + bias[h];
}

// ---------------------------------------------------------------------------
// K2: fp16 mma.sync GEMM + tanh + v-dot epilogue.
// CTA 128x128, 4 warps (2m x 2n), warp tile 64x64, k-chunk 64,
// 3-stage cp.async pipeline + ks-level fragment double buffering.
// 2 CTAs resident per SM (barrier bubbles of one filled by the other).
// grid (8 ntiles [x fastest -> A reuse in L2], 512 mtiles), 128 threads.
// ---------------------------------------------------------------------------
__global__ void __launch_bounds__(NTHREADS, 2)
gemm_scores_mma(const float* __restrict__ vW){
    extern __shared__ char smem[];
    const uint32_t sb = smem_u32(smem);
    float (*s_row)[2] = (float(*)[2])(smem + SROW_OFF);

    const int tid  = threadIdx.x;
    const int lane = tid & 31, wid = tid >> 5;
    const int wm = wid & 1, wn = wid >> 1;       // 2 x 2
    const int mbase = wm * 64, nbase = wn * 64;
    const int g = lane >> 2, t = lane & 3;
    const int ntile = blockIdx.x, mtile = blockIdx.y;
    const int m0 = mtile * M_CTA, n0 = ntile * N_CTA;

    const __half* Ag = g_encF + (size_t)m0 * NH;
    const __half* Bg = g_w2F + (size_t)n0 * NH;

    float c[4][8][4];
    #pragma unroll
    for (int i = 0; i < 4; i++)
        #pragma unroll
        for (int j = 0; j < 8; j++)
            #pragma unroll
            for (int k = 0; k < 4; k++) c[i][j][k] = 0.f;

    // ldsm base offsets (swizzled); ks folded via XOR with ks<<5
    const uint32_t r15 = (uint32_t)(lane & 15);
    const uint32_t c0  = ((uint32_t)lane >> 4) * 16;
    uint32_t relA[4], relB[4];
    #pragma unroll
    for (int mf = 0; mf < 4; mf++){
        uint32_t row = (uint32_t)mbase + mf * 16 + r15;
        relA[mf] = row * 128 + (c0 ^ ((row & 7) << 4));
    }
    #pragma unroll
    for (int nq = 0; nq < 4; nq++){
        uint32_t row = (uint32_t)nbase + nq * 16 + r15;
        relB[nq] = row * 128 + (c0 ^ ((row & 7) << 4));
    }

    // cp.async bases: 128 threads cover 16 rows x 8 cols; i advances 16 rows
    // (+2048B smem, +16*NH global; row&7 invariant so swizzle offset is reusable)
    const int row0 = tid >> 3, cu0 = tid & 7;
    const uint32_t cprel = (uint32_t)(row0 * 128) + (((uint32_t)cu0 * 16) ^ (((uint32_t)row0 & 7) << 4));
    const size_t go0 = (size_t)row0 * NH + cu0 * 8;

    auto prefetch = [&](int ci, int st){
        const uint32_t so = sb + st * STAGESZ;
        const __half* pa = Ag + go0 + ci * KCH;
        const __half* pb = Bg + go0 + ci * KCH;
        #pragma unroll
        for (int i = 0; i < 8; i++)
            cp16(so + cprel + i * 2048, pa + (size_t)i * (16 * NH));
        #pragma unroll
        for (int i = 0; i < 8; i++)
            cp16(so + SB_OFF + cprel + i * 2048, pb + (size_t)i * (16 * NH));
    };

    // fragment double buffer: slot = ks & 1
    uint32_t ah[2][4][4], bh[2][4][4];

    auto load_frags = [&](int slot, uint32_t soA, int ks){
        const uint32_t soB = soA + SB_OFF;
        const uint32_t kx = (uint32_t)(ks << 5);
        #pragma unroll
        for (int nq = 0; nq < 4; nq++)
            ldsm4(bh[slot][nq], soB + (relB[nq] ^ kx));
        #pragma unroll
        for (int mf = 0; mf < 4; mf++)
            ldsm4(ah[slot][mf], soA + (relA[mf] ^ kx));
    };
    auto do_mma = [&](int slot){
        #pragma unroll
        for (int mf = 0; mf < 4; mf++){
            #pragma unroll
            for (int nf = 0; nf < 8; nf++){
                const int nq = nf >> 1, hi = nf & 1;
                mma16816(c[mf][nf], ah[slot][mf], bh[slot][nq][hi], bh[slot][nq][hi+2]);
            }
        }
    };

    prefetch(0, 0); cp_commit();
    prefetch(1, 1); cp_commit();

    cp_wait<1>();
    __syncthreads();
    load_frags(0, sb /*stage 0*/, 0);           // ks0 -> slot 0

    for (int ci = 0; ci < NCHUNK; ci++){
        // stage (ci+2)%3 == (ci-1)%3: reads finished before prev iter's sync
        if (ci + 2 < NCHUNK) prefetch(ci + 2, (ci + 2) % 3);
        cp_commit();

        const uint32_t soA = sb + (ci % 3) * STAGESZ;

        load_frags(1, soA, 1);  do_mma(0);      // ks1 -> s1 | mma ks0 (s0)
        load_frags(0, soA, 2);  do_mma(1);      // ks2 -> s0 | mma ks1 (s1)
        load_frags(1, soA, 3);  do_mma(0);      // ks3 -> s1 | mma ks2 (s0)

        if (ci + 1 < NCHUNK){
            cp_wait<1>();                       // group ci+1 complete
            __syncthreads();
            load_frags(0, sb + ((ci + 1) % 3) * STAGESZ, 0);   // next ks0 -> s0
        }
        do_mma(1);                              // mma ks3 (s1)
    }

    // Epilogue: partial scores over this CTA's 128 n-cols (tanh.approx).
    float rs0[4] = {0,0,0,0}, rs1[4] = {0,0,0,0};
    #pragma unroll
    for (int mf = 0; mf < 4; mf++){
        const int mlo = mbase + mf*16 + g;
        const int blo = mlo & 31;
        const int bhi = (mlo + 8) & 31;
        #pragma unroll
        for (int nf = 0; nf < 8; nf++){
            const int ngl = n0 + nbase + nf*8 + 2*t;
            float v0 = __ldg(&vW[ngl]), v1 = __ldg(&vW[ngl+1]);
            float h00 = g_hidc[blo*NH + ngl], h01 = g_hidc[blo*NH + ngl + 1];
            float h10 = g_hidc[bhi*NH + ngl], h11 = g_hidc[bhi*NH + ngl + 1];
            rs0[mf] += tanh_ap(c[mf][nf][0] + h00) * v0 + tanh_ap(c[mf][nf][1] + h01) * v1;
            rs1[mf] += tanh_ap(c[mf][nf][2] + h10) * v0 + tanh_ap(c[mf][nf][3] + h11) * v1;
        }
    }
    #pragma unroll
    for (int mf = 0; mf < 4; mf++){
        rs0[mf] += __shfl_xor_sync(0xffffffffu, rs0[mf], 1);
        rs0[mf] += __shfl_xor_sync(0xffffffffu, rs0[mf], 2);
        rs1[mf] += __shfl_xor_sync(0xffffffffu, rs1[mf], 1);
        rs1[mf] += __shfl_xor_sync(0xffffffffu, rs1[mf], 2);
    }
    __syncthreads();
    if (t == 0){
        #pragma unroll
        for (int mf = 0; mf < 4; mf++){
            s_row[mbase + mf*16 + g    ][wn] = rs0[mf];
            s_row[mbase + mf*16 + g + 8][wn] = rs1[mf];
        }
    }
    __syncthreads();
    {
        float s = s_row[tid][0] + s_row[tid][1];
        g_part[(size_t)ntile * MTOT + m0 + tid] = s;
    }
}

// ---------------------------------------------------------------------------
// K3: sum partials -> softmax over S per batch -> attn_weights; zero ctx
// ---------------------------------------------------------------------------
__global__ void softmax_kernel(float* __restrict__ w_out, float* __restrict__ ctx){
    __shared__ float sc[NS];
    __shared__ float red[256];
    const int b = blockIdx.x, tid = threadIdx.x;

    #pragma unroll
    for (int i = tid; i < NH; i += 256) ctx[b * NH + i] = 0.f;

    float lmax = -1e30f;
    for (int s = tid; s < NS; s += 256){
        float v = 0.f;
        #pragma unroll
        for (int nt = 0; nt < NTILES; nt++)
            v += g_part[(size_t)nt * MTOT + s * NB + b];
        sc[s] = v;
        lmax = fmaxf(lmax, v);
    }
    red[tid] = lmax; __syncthreads();
    for (int o = 128; o > 0; o >>= 1){
        if (tid < o) red[tid] = fmaxf(red[tid], red[tid + o]);
        __syncthreads();
    }
    const float mx = red[0];
    __syncthreads();

    float lsum = 0.f;
    for (int s = tid; s < NS; s += 256){
        float e = expf(sc[s] - mx);
        sc[s] = e;
        lsum += e;
    }
    red[tid] = lsum; __syncthreads();
    for (int o = 128; o > 0; o >>= 1){
        if (tid < o) red[tid] = red[tid] + red[tid + o];
        __syncthreads();
    }
    const float inv = 1.f / red[0];
    for (int s = tid; s < NS; s += 256)
        w_out[b * NS + s] = sc[s] * inv;
}

// ---------------------------------------------------------------------------
// K4: context[b][h] += sum_{s in chunk} w[b][s] * enc_fp16[s][b][h]  (atomic)
// ---------------------------------------------------------------------------
__global__ void context_kernel(const float* __restrict__ w,
                               float* __restrict__ ctx){
    const int b = blockIdx.y;
    const int h = blockIdx.x * 256 + threadIdx.x * 2;
    const int s0 = blockIdx.z * 128;
    const __half2* e = (const __half2*)(g_encF + (size_t)s0 * (NB*NH) + (size_t)b * NH + h);
    const float* wb = w + (size_t)b * NS + s0;
    const size_t stride2 = (NB*NH) / 2;
    float ax = 0.f, ay = 0.f;
    #pragma unroll 8
    for (int j = 0; j < 128; j++){
        float2 f = __half22float2(e[(size_t)j * stride2]);
        float wv = wb[j];
        ax += wv * f.x;
        ay += wv * f.y;
    }
    atomicAdd(&ctx[(size_t)b * NH + h], ax);
    atomicAdd(&ctx[(size_t)b * NH + h + 1], ay);
}

// ---------------------------------------------------------------------------
extern "C" void kernel_launch(void* const* d_in, const int* in_sizes, int n_in,
                              void* d_out, int out_size){
    const float* hidden = (const float*)d_in[0];   // [B,H]
    const float* enc    = (const float*)d_in[1];   // [S,B,H]
    const float* attn_W = (const float*)d_in[2];   // [H,2H]
    const float* attn_b = (const float*)d_in[3];   // [H]
    const float* v_W    = (const float*)d_in[4];   // [1,H]
    float* out = (float*)d_out;
    float* ctx = out;                 // [B,H]
    float* wts = out + NB*NH;         // [B,S]

    cudaFuncSetAttribute(gemm_scores_mma, cudaFuncAttributeMaxDynamicSharedMemorySize, SMEM_TOTAL);

    cvt_enc_kernel<<<(MTOT*(NH/8))/256, 256>>>(enc);
    cvt_w2_kernel<<<(NH*(NH/8))/256, 256>>>(attn_W);
    hidc_kernel<<<128, 256>>>(hidden, attn_W, attn_b);
    gemm_scores_mma<<<dim3(NTILES, MTOT/M_CTA), NTHREADS, SMEM_TOTAL>>>(v_W);
    softmax_kernel<<<NB, 256>>>(wts, ctx);
    context_kernel<<<dim3(NH/256, NB, NS/128), 128>>>(wts, ctx);
}